// round 15
// baseline (speedup 1.0000x reference)
#include <cuda_runtime.h>
#include <math.h>

#define B_ 64
#define T_ 1024
#define I_ 128
#define H_ 512
#define O_ 128
#define GRID0 128
#define NT 512

typedef unsigned long long ull;

// ---- scratch (device globals: allocation-free) ----
__device__ float g_xT[T_ * I_ * B_];      // x transposed: [t][i][b]
__device__ float g_h0buf[2 * H_ * B_];    // layer0 h double buffer
__device__ float g_h1[T_ * H_ * B_];      // layer1 h history: [t][h][b]
__device__ unsigned g_bar_count;
__device__ unsigned g_bar_sense;

// ---- packed f32x2 helpers (FC phase) ----
__device__ __forceinline__ ull pack2(float x) {
    ull r; unsigned u = __float_as_uint(x);
    asm("mov.b64 %0, {%1, %1};" : "=l"(r) : "r"(u));
    return r;
}
__device__ __forceinline__ ull pack_ab(float a, float b) {
    ull r;
    asm("mov.b64 %0, {%1, %2};" : "=l"(r)
        : "r"(__float_as_uint(a)), "r"(__float_as_uint(b)));
    return r;
}
__device__ __forceinline__ void ffma2(ull &acc, ull a, ull w) {
    asm("fma.rn.f32x2 %0, %1, %2, %0;" : "+l"(acc) : "l"(a), "l"(w));
}
__device__ __forceinline__ ull addx2(ull a, ull b) {
    ull r;
    asm("add.rn.f32x2 %0, %1, %2;" : "=l"(r) : "l"(a), "l"(b));
    return r;
}
__device__ __forceinline__ float lo2(ull v) { return __uint_as_float((unsigned)v); }
__device__ __forceinline__ float hi2(ull v) { return __uint_as_float((unsigned)(v >> 32)); }

__device__ __forceinline__ float sigm(float x) {
    return __fdividef(1.f, 1.f + __expf(-x));
}
__device__ __forceinline__ float tanh_(float x) {
    return __fdividef(2.f, 1.f + __expf(-2.f * x)) - 1.f;
}

#define GBAR1() asm volatile("bar.sync 1, 256;" ::: "memory")
#define GBAR2() asm volatile("bar.sync 2, 256;" ::: "memory")

// ---- full grid barrier (identical to R12/R14 passing kernels) ----
__device__ __forceinline__ void gridbar(unsigned &sense) {
    __syncthreads();
    if (threadIdx.x == 0) {
        unsigned s = sense ^ 1u;
        sense = s;
        unsigned old;
        asm volatile("atom.release.gpu.global.add.u32 %0, [%1], %2;"
                     : "=r"(old) : "l"(&g_bar_count), "r"(1u));
        if (old == GRID0 - 1u) {
            g_bar_count = 0u;
            asm volatile("st.release.gpu.global.u32 [%0], %1;"
                         :: "l"(&g_bar_sense), "r"(s));
        } else {
            unsigned v;
            do {
                asm volatile("ld.acquire.gpu.global.u32 %0, [%1];"
                             : "=r"(v) : "l"(&g_bar_sense));
            } while (v != s);
        }
    }
    __syncthreads();
}

// ---- 3xTF32 helpers ----
__device__ __forceinline__ unsigned tf32_hi(float v) {
    unsigned r; asm("cvt.rna.tf32.f32 %0, %1;" : "=r"(r) : "f"(v));
    return r;
}
__device__ __forceinline__ unsigned tf32_lo(float v, unsigned h) {
    float d = v - __uint_as_float(h);
    unsigned r; asm("cvt.rna.tf32.f32 %0, %1;" : "=r"(r) : "f"(d));
    return r;
}
__device__ __forceinline__ void mma8(float* c,
    unsigned a0, unsigned a1, unsigned a2, unsigned a3,
    unsigned b0, unsigned b1)
{
    asm volatile(
        "mma.sync.aligned.m16n8k8.row.col.f32.tf32.tf32.f32 "
        "{%0,%1,%2,%3}, {%4,%5,%6,%7}, {%8,%9}, {%0,%1,%2,%3};"
        : "+f"(c[0]), "+f"(c[1]), "+f"(c[2]), "+f"(c[3])
        : "r"(a0), "r"(a1), "r"(a2), "r"(a3), "r"(b0), "r"(b1));
}

// ---- 3xTF32 gate GEMM over one segment: D[64b][16r] += in^T · W ----
// A[m=batch][k] = in[k][b] (global, .cg), B[k][n=gaterow] = Wt[k][16] (smem).
// Warp wi covers k in [wi*kpw, (wi+1)*kpw); kpw multiple of 8.
// c[mt][nt][4]: m-tile mt (batches 16mt..+15), n-tile nt (rows 8nt..+7).
// Lane: qd = lane>>2, tq = lane&3 (PTX m16n8k8 fragment coords).
__device__ __forceinline__ void gemmT(
    float c[4][2][4], const float* __restrict__ src,
    const float* __restrict__ Wt, int kpw, int wi, int qd, int tq)
{
    const float* ab = src + wi * kpw * B_ + qd;
    const float* wb = Wt + wi * kpw * 16 + qd;
    for (int ks = 0; ks < kpw; ks += 8) {
        const float* ak = ab + ks * B_ + tq * B_;
        const float* wk = wb + ks * 16;
        // B fragments (2 n-tiles): b0 = B[k=tq][n], b1 = B[k=tq+4][n]
        float bv00 = wk[tq * 16];            // nt=0
        float bv01 = wk[(tq + 4) * 16];
        float bv10 = wk[tq * 16 + 8];        // nt=1
        float bv11 = wk[(tq + 4) * 16 + 8];
        unsigned bh00 = tf32_hi(bv00), bl00 = tf32_lo(bv00, bh00);
        unsigned bh01 = tf32_hi(bv01), bl01 = tf32_lo(bv01, bh01);
        unsigned bh10 = tf32_hi(bv10), bl10 = tf32_lo(bv10, bh10);
        unsigned bh11 = tf32_hi(bv11), bl11 = tf32_lo(bv11, bh11);
#pragma unroll
        for (int mt = 0; mt < 4; mt++) {
            // A frag: a0=A[qd][tq], a1=A[qd+8][tq], a2=A[qd][tq+4], a3=A[qd+8][tq+4]
            const float* am = ak + mt * 16;
            float a0 = __ldcg(am);
            float a1 = __ldcg(am + 8);
            float a2 = __ldcg(am + 4 * B_);
            float a3 = __ldcg(am + 4 * B_ + 8);
            unsigned h0 = tf32_hi(a0), l0 = tf32_lo(a0, h0);
            unsigned h1 = tf32_hi(a1), l1 = tf32_lo(a1, h1);
            unsigned h2 = tf32_hi(a2), l2 = tf32_lo(a2, h2);
            unsigned h3 = tf32_hi(a3), l3 = tf32_lo(a3, h3);
            mma8(c[mt][0], h0, h1, h2, h3, bh00, bh01);
            mma8(c[mt][0], l0, l1, l2, l3, bh00, bh01);
            mma8(c[mt][0], h0, h1, h2, h3, bl00, bl01);
            mma8(c[mt][1], h0, h1, h2, h3, bh10, bh11);
            mma8(c[mt][1], l0, l1, l2, l3, bh10, bh11);
            mma8(c[mt][1], h0, h1, h2, h3, bl10, bl11);
        }
    }
}

// ---------------------------------------------------------------------------
// Mega kernel: transpose + both LSTM layers (warp-specialized, tensor) + FC.
__global__ void __launch_bounds__(NT, 1) mega_kernel(
    const float* __restrict__ x,
    const float* __restrict__ W_ih0, const float* __restrict__ W_hh0,
    const float* __restrict__ b_ih0, const float* __restrict__ b_hh0,
    const float* __restrict__ W_ih1, const float* __restrict__ W_hh1,
    const float* __restrict__ b_ih1, const float* __restrict__ b_hh1,
    const float* __restrict__ Wfc,  const float* __restrict__ bfc,
    float* __restrict__ out)
{
    extern __shared__ float sm[];
    float* Wt0   = sm;                 // [640][16]  = 10240 floats
    float* Wt1   = sm + 10240;         // [1024][16] = 16384 floats
    float* bias0 = sm + 26624;         // 16
    float* bias1 = sm + 26640;         // 16
    float* gs0   = sm + 26656;         // 16 x 64 = 1024
    float* gs1   = sm + 27680;         // 16 x 64 = 1024
    ull*   red   = (ull*)(sm + 28704); // 2 groups * 8 warps * 512 ull = 64KB

    const int tid  = threadIdx.x;
    const int hj0  = blockIdx.x * 4;
    const int grp  = tid >> 8;         // 0: layer0, 1: layer1
    const int gtid = tid & 255;
    const int wi   = gtid >> 5;        // group-warp 0..7
    const int lane = gtid & 31;
    const int qd   = lane >> 2;        // mma quad 0..7
    const int tq   = lane & 3;         // mma thread-in-quad 0..3

    unsigned sense = 0;
    if (tid == 0) sense = *(volatile unsigned*)&g_bar_sense;

    // ---- transpose phase: x[b][t][i] -> g_xT[t][i][b] (tile in Wt1 region)
    {
        float (*tile)[I_ + 1] = (float (*)[I_ + 1])Wt1;   // 64 x 129 = 8256
        for (int t = blockIdx.x; t < T_; t += GRID0) {
            __syncthreads();
            for (int idx = tid; idx < B_ * I_; idx += NT) {
                int b = idx >> 7, i = idx & 127;
                tile[b][i] = x[(b * T_ + t) * I_ + i];
            }
            __syncthreads();
            for (int idx = tid; idx < B_ * I_; idx += NT) {
                int b = idx & 63, i = idx >> 6;
                g_xT[t * I_ * B_ + i * B_ + b] = tile[b][i];
            }
        }
    }
    gridbar(sense);

    // ---- transposed weight slices: Wt[k][r], r = gate*4 + c
    for (int idx = tid; idx < 640 * 16; idx += NT) {
        int k = idx >> 4, r = idx & 15;
        int grow = (r >> 2) * H_ + hj0 + (r & 3);
        Wt0[idx] = (k < I_) ? W_ih0[grow * I_ + k]
                            : W_hh0[grow * H_ + (k - I_)];
    }
    for (int idx = tid; idx < 1024 * 16; idx += NT) {
        int k = idx >> 4, r = idx & 15;
        int grow = (r >> 2) * H_ + hj0 + (r & 3);
        Wt1[idx] = (k < H_) ? W_ih1[grow * H_ + k]
                            : W_hh1[grow * H_ + (k - H_)];
    }
    if (tid < 16) {
        int grow = (tid >> 2) * H_ + hj0 + (tid & 3);
        bias0[tid] = b_ih0[grow] + b_hh0[grow];
        bias1[tid] = b_ih1[grow] + b_hh1[grow];
    }
    __syncthreads();

    // ---- main loop: group0 does layer0 at t=k, group1 does layer1 at s=k-1,
    //      CONCURRENTLY. Group-local named barriers; one gridbar per iter.
    float2 cst = make_float2(0.f, 0.f);
    ull* redG    = red + grp * 4096;
    float* gsG   = grp ? gs1 : gs0;
    float* biasG = grp ? bias1 : bias0;
    const int c4_a = gtid >> 5;        // act unit (gtid<128): h-col 0..3
    const int bp_a = gtid & 31;        //                      batch-pair

    for (int k = 0; k <= T_; ++k) {
        const bool active = grp ? (k >= 1) : (k < T_);
        if (active) {
            float c[4][2][4];
#pragma unroll
            for (int mt = 0; mt < 4; mt++)
#pragma unroll
                for (int nt = 0; nt < 2; nt++)
#pragma unroll
                    for (int i = 0; i < 4; i++) c[mt][nt][i] = 0.f;

            if (grp == 0) {
                gemmT(c, g_xT + k * I_ * B_, Wt0, 16, wi, qd, tq);
                if (k > 0)
                    gemmT(c, g_h0buf + ((k - 1) & 1) * H_ * B_,
                          Wt0 + I_ * 16, 64, wi, qd, tq);
            } else {
                gemmT(c, g_h0buf + ((k - 1) & 1) * H_ * B_,
                      Wt1, 64, wi, qd, tq);
                if (k >= 2)
                    gemmT(c, g_h1 + (k - 2) * H_ * B_,
                          Wt1 + H_ * 16, 64, wi, qd, tq);
            }

            // dump C fragments to red: entry ull = rows (2rp, 2rp+1) @ batch b
            {
                ull* rw = redG + wi * 512;
#pragma unroll
                for (int mt = 0; mt < 4; mt++)
#pragma unroll
                    for (int nt = 0; nt < 2; nt++) {
                        int rp = nt * 4 + tq;
                        int b  = mt * 16 + qd;
                        rw[rp * 64 + b]     = pack_ab(c[mt][nt][0], c[mt][nt][1]);
                        rw[rp * 64 + b + 8] = pack_ab(c[mt][nt][2], c[mt][nt][3]);
                    }
            }
            if (grp == 0) GBAR1(); else GBAR2();

            // stage1: 256 threads, 2 units each (unit = row-pair x batch)
#pragma unroll
            for (int uu = 0; uu < 2; uu++) {
                int u = gtid + uu * 256;
                int rp = u >> 6, b = u & 63;
                const ull* rr = redG + rp * 64 + b;
                ull v = rr[0];
#pragma unroll
                for (int ww = 1; ww < 8; ww++) v = addx2(v, rr[ww * 512]);
                float2 bb = *(const float2*)(biasG + 2 * rp);
                v = addx2(v, pack_ab(bb.x, bb.y));
                gsG[(2 * rp) * 64 + b]     = lo2(v);
                gsG[(2 * rp + 1) * 64 + b] = hi2(v);
            }
            if (grp == 0) GBAR1(); else GBAR2();

            // activation: 128 threads of the group
            if (gtid < 128) {
                float2 xi = *(const float2*)(gsG + (0  + c4_a) * 64 + 2 * bp_a);
                float2 xf = *(const float2*)(gsG + (4  + c4_a) * 64 + 2 * bp_a);
                float2 xg = *(const float2*)(gsG + (8  + c4_a) * 64 + 2 * bp_a);
                float2 xo = *(const float2*)(gsG + (12 + c4_a) * 64 + 2 * bp_a);
                float i0 = sigm(xi.x), i1 = sigm(xi.y);
                float f0 = sigm(xf.x), f1 = sigm(xf.y);
                float g0 = tanh_(xg.x), g1 = tanh_(xg.y);
                float o0 = sigm(xo.x), o1 = sigm(xo.y);
                cst.x = f0 * cst.x + i0 * g0;
                cst.y = f1 * cst.y + i1 * g1;
                float* hdst = grp
                    ? (g_h1 + (k - 1) * H_ * B_ + hj0 * B_)
                    : (g_h0buf + (k & 1) * H_ * B_ + hj0 * B_);
                *(float2*)(hdst + c4_a * B_ + 2 * bp_a) =
                    make_float2(o0 * tanh_(cst.x), o1 * tanh_(cst.y));
            }
        }
        gridbar(sense);
    }

    // ---- FC phase: out[b][t][o] = sum_h h1[t][h][b] * Wfc[o][h] + bfc[o]
    {
        float* w_s = sm;                  // 128 x 65 = 8320
        float* h_s = sm + 8320;           // 64 x 64  = 4096
        float* o_s = sm + 12416;          // 64 x 128 = 8192
        const int ot = tid & 15;          // o = ot + j*16
        const int bt = (tid >> 4) & 15;   // batches bt*4..+3 (tid<256 only)

        for (int t = blockIdx.x; t < T_; t += GRID0) {
            ull acc[16];
#pragma unroll
            for (int i = 0; i < 16; i++) acc[i] = 0ull;

            for (int kb = 0; kb < H_; kb += 64) {
                __syncthreads();
                for (int idx = tid; idx < O_ * 64; idx += NT) {
                    int o = idx >> 6, kk = idx & 63;
                    w_s[o * 65 + kk] = Wfc[o * H_ + kb + kk];
                }
                for (int idx = tid; idx < 64 * B_; idx += NT) {
                    h_s[idx] = g_h1[(t * H_ + kb) * B_ + idx];
                }
                __syncthreads();
                if (tid < 256) {
#pragma unroll 4
                    for (int kk = 0; kk < 64; kk++) {
                        ulonglong2 A = *(const ulonglong2*)(h_s + kk * B_ + bt * 4);
#pragma unroll
                        for (int j = 0; j < 8; j++) {
                            ull ww = pack2(w_s[(ot + j * 16) * 65 + kk]);
                            ffma2(acc[j * 2 + 0], A.x, ww);
                            ffma2(acc[j * 2 + 1], A.y, ww);
                        }
                    }
                }
            }
            __syncthreads();
            if (tid < 256) {
#pragma unroll
                for (int j = 0; j < 8; j++) {
                    int o = ot + j * 16;
                    o_s[(bt * 4 + 0) * O_ + o] = lo2(acc[j * 2 + 0]);
                    o_s[(bt * 4 + 1) * O_ + o] = hi2(acc[j * 2 + 0]);
                    o_s[(bt * 4 + 2) * O_ + o] = lo2(acc[j * 2 + 1]);
                    o_s[(bt * 4 + 3) * O_ + o] = hi2(acc[j * 2 + 1]);
                }
            }
            __syncthreads();
            for (int idx = tid; idx < B_ * O_; idx += NT) {
                int b = idx >> 7, o = idx & 127;
                out[(b * T_ + t) * O_ + o] = o_s[idx] + __ldg(&bfc[o]);
            }
        }
    }
}

// ---------------------------------------------------------------------------
extern "C" void kernel_launch(void* const* d_in, const int* in_sizes, int n_in,
                              void* d_out, int out_size) {
    const float* x     = (const float*)d_in[0];
    const float* W_ih0 = (const float*)d_in[1];
    const float* W_hh0 = (const float*)d_in[2];
    const float* b_ih0 = (const float*)d_in[3];
    const float* b_hh0 = (const float*)d_in[4];
    const float* W_ih1 = (const float*)d_in[5];
    const float* W_hh1 = (const float*)d_in[6];
    const float* b_ih1 = (const float*)d_in[7];
    const float* b_hh1 = (const float*)d_in[8];
    const float* W_fc  = (const float*)d_in[9];
    const float* b_fc  = (const float*)d_in[10];
    float* out = (float*)d_out;

    size_t smem = (size_t)(28704 * 4 + 65536);   // 180352 B
    cudaFuncSetAttribute(mega_kernel, cudaFuncAttributeMaxDynamicSharedMemorySize, (int)smem);

    mega_kernel<<<GRID0, NT, smem>>>(x, W_ih0, W_hh0, b_ih0, b_hh0,
                                     W_ih1, W_hh1, b_ih1, b_hh1,
                                     W_fc, b_fc, out);
}

// round 16
// speedup vs baseline: 1.2353x; 1.2353x over previous
#include <cuda_runtime.h>
#include <math.h>

#define B_ 64
#define T_ 1024
#define I_ 128
#define H_ 512
#define O_ 128
#define GRID0 128
#define NT 512

typedef unsigned long long ull;

// ---- scratch (device globals: allocation-free) ----
__device__ unsigned g_xhb[T_ * 64 * B_];    // x bf16-hi packed: [t][kp][b]
__device__ unsigned g_xlb[T_ * 64 * B_];    // x bf16-lo packed
__device__ unsigned g_h0hb[2 * 256 * B_];   // layer0 h hi, double buffered
__device__ unsigned g_h0lb[2 * 256 * B_];   // layer0 h lo
__device__ unsigned g_h1hb[T_ * 256 * B_];  // layer1 h hi history
__device__ unsigned g_h1lb[T_ * 256 * B_];  // layer1 h lo history
__device__ float    g_h1[T_ * H_ * B_];     // layer1 h fp32 (FC input)
__device__ unsigned g_bar_count;
__device__ unsigned g_bar_sense;

// ---- packed f32x2 helpers (FC phase + reduction) ----
__device__ __forceinline__ ull pack2(float x) {
    ull r; unsigned u = __float_as_uint(x);
    asm("mov.b64 %0, {%1, %1};" : "=l"(r) : "r"(u));
    return r;
}
__device__ __forceinline__ ull pack_ab(float a, float b) {
    ull r;
    asm("mov.b64 %0, {%1, %2};" : "=l"(r)
        : "r"(__float_as_uint(a)), "r"(__float_as_uint(b)));
    return r;
}
__device__ __forceinline__ void ffma2(ull &acc, ull a, ull w) {
    asm("fma.rn.f32x2 %0, %1, %2, %0;" : "+l"(acc) : "l"(a), "l"(w));
}
__device__ __forceinline__ ull addx2(ull a, ull b) {
    ull r;
    asm("add.rn.f32x2 %0, %1, %2;" : "=l"(r) : "l"(a), "l"(b));
    return r;
}
__device__ __forceinline__ float lo2(ull v) { return __uint_as_float((unsigned)v); }
__device__ __forceinline__ float hi2(ull v) { return __uint_as_float((unsigned)(v >> 32)); }

// ---- bf16 pack helpers: u32 = {hi16 = bf16(vhi), lo16 = bf16(vlo)} ----
__device__ __forceinline__ unsigned bfpack(float vlo, float vhi) {
    unsigned r;
    asm("cvt.rn.bf16x2.f32 %0, %1, %2;" : "=r"(r) : "f"(vhi), "f"(vlo));
    return r;
}
__device__ __forceinline__ float bflo(unsigned p) { return __uint_as_float(p << 16); }
__device__ __forceinline__ float bfhi(unsigned p) { return __uint_as_float(p & 0xffff0000u); }

__device__ __forceinline__ float sigm(float x) {
    return __fdividef(1.f, 1.f + __expf(-x));
}
__device__ __forceinline__ float tanh_(float x) {
    return __fdividef(2.f, 1.f + __expf(-2.f * x)) - 1.f;
}

#define GBAR1() asm volatile("bar.sync 1, 256;" ::: "memory")
#define GBAR2() asm volatile("bar.sync 2, 256;" ::: "memory")

// ---- full grid barrier (identical to R12/R14 passing kernels) ----
__device__ __forceinline__ void gridbar(unsigned &sense) {
    __syncthreads();
    if (threadIdx.x == 0) {
        unsigned s = sense ^ 1u;
        sense = s;
        unsigned old;
        asm volatile("atom.release.gpu.global.add.u32 %0, [%1], %2;"
                     : "=r"(old) : "l"(&g_bar_count), "r"(1u));
        if (old == GRID0 - 1u) {
            g_bar_count = 0u;
            asm volatile("st.release.gpu.global.u32 [%0], %1;"
                         :: "l"(&g_bar_sense), "r"(s));
        } else {
            unsigned v;
            do {
                asm volatile("ld.acquire.gpu.global.u32 %0, [%1];"
                             : "=r"(v) : "l"(&g_bar_sense));
            } while (v != s);
        }
    }
    __syncthreads();
}

// ---- bf16 m16n8k16 MMA ----
__device__ __forceinline__ void mma16(float* c,
    unsigned a0, unsigned a1, unsigned a2, unsigned a3,
    unsigned b0, unsigned b1)
{
    asm volatile(
        "mma.sync.aligned.m16n8k16.row.col.f32.bf16.bf16.f32 "
        "{%0,%1,%2,%3}, {%4,%5,%6,%7}, {%8,%9}, {%0,%1,%2,%3};"
        : "+f"(c[0]), "+f"(c[1]), "+f"(c[2]), "+f"(c[3])
        : "r"(a0), "r"(a1), "r"(a2), "r"(a3), "r"(b0), "r"(b1));
}

// ---- split-bf16 gate GEMM: D[64b][16r] += in^T · W over one segment ----
// A[m=batch][k] = in[k][b] as packed k-pairs: srcH/srcL[kp][b] u32 (global,.cg)
// B[k][n=gaterow]: WH/WL[kp][16] u32 (smem).
// Warp covers kp in [kp0, kp0 + nsteps*8). Lane: qd = lane>>2, tq = lane&3.
// c[mt][nt][4]: batches 16mt+{qd,qd+8}, gate rows 8nt+{2tq,2tq+1}.
__device__ __forceinline__ void gemmB(
    float c[4][2][4],
    const unsigned* __restrict__ srcH, const unsigned* __restrict__ srcL,
    const unsigned* __restrict__ WH,   const unsigned* __restrict__ WL,
    int kp0, int nsteps, int qd, int tq)
{
    for (int s = 0; s < nsteps; s++) {
        int kpb = kp0 + s * 8;
        const unsigned* ah = srcH + (kpb + tq) * B_ + qd;
        const unsigned* al = srcL + (kpb + tq) * B_ + qd;
        const unsigned* wh = WH + (kpb + tq) * 16;
        const unsigned* wl = WL + (kpb + tq) * 16;
        unsigned bh[2][2], bl[2][2];
#pragma unroll
        for (int nt = 0; nt < 2; nt++) {
            int n = nt * 8 + qd;
            bh[nt][0] = wh[n];      bh[nt][1] = wh[64 + n];
            bl[nt][0] = wl[n];      bl[nt][1] = wl[64 + n];
        }
#pragma unroll
        for (int mt = 0; mt < 4; mt++) {
            const unsigned* am = ah + mt * 16;
            unsigned aH0 = __ldcg(am);
            unsigned aH1 = __ldcg(am + 8);
            unsigned aH2 = __ldcg(am + 4 * B_);
            unsigned aH3 = __ldcg(am + 4 * B_ + 8);
            const unsigned* amL = al + mt * 16;
            unsigned aL0 = __ldcg(amL);
            unsigned aL1 = __ldcg(amL + 8);
            unsigned aL2 = __ldcg(amL + 4 * B_);
            unsigned aL3 = __ldcg(amL + 4 * B_ + 8);
#pragma unroll
            for (int nt = 0; nt < 2; nt++) {
                mma16(c[mt][nt], aH0, aH1, aH2, aH3, bh[nt][0], bh[nt][1]);
                mma16(c[mt][nt], aL0, aL1, aL2, aL3, bh[nt][0], bh[nt][1]);
                mma16(c[mt][nt], aH0, aH1, aH2, aH3, bl[nt][0], bl[nt][1]);
            }
        }
    }
}

// ---------------------------------------------------------------------------
// Mega kernel: transpose + both LSTM layers (warp-specialized, bf16 MMA) + FC.
__global__ void __launch_bounds__(NT, 1) mega_kernel(
    const float* __restrict__ x,
    const float* __restrict__ W_ih0, const float* __restrict__ W_hh0,
    const float* __restrict__ b_ih0, const float* __restrict__ b_hh0,
    const float* __restrict__ W_ih1, const float* __restrict__ W_hh1,
    const float* __restrict__ b_ih1, const float* __restrict__ b_hh1,
    const float* __restrict__ Wfc,  const float* __restrict__ bfc,
    float* __restrict__ out)
{
    extern __shared__ float sm[];
    unsigned* WtH0 = (unsigned*)sm;            // [320][16] = 5120 u32
    unsigned* WtL0 = (unsigned*)sm + 5120;     // 5120
    unsigned* WtH1 = (unsigned*)sm + 10240;    // [512][16] = 8192
    unsigned* WtL1 = (unsigned*)sm + 18432;    // 8192  -> ends at 26624
    float* bias0 = sm + 26624;                 // 16
    float* bias1 = sm + 26640;                 // 16
    float* gs0   = sm + 26656;                 // 16 x 64 = 1024
    float* gs1   = sm + 27680;                 // 16 x 64 = 1024
    ull*   red   = (ull*)(sm + 28704);         // 2 * 8 * 512 ull = 65536 B

    const int tid  = threadIdx.x;
    const int hj0  = blockIdx.x * 4;
    const int grp  = tid >> 8;         // 0: layer0, 1: layer1
    const int gtid = tid & 255;
    const int wi   = gtid >> 5;        // group-warp 0..7
    const int lane = gtid & 31;
    const int qd   = lane >> 2;        // mma quad 0..7
    const int tq   = lane & 3;         // thread-in-quad 0..3

    unsigned sense = 0;
    if (tid == 0) sense = *(volatile unsigned*)&g_bar_sense;

    // ---- transpose phase: x[b][t][i] -> packed bf16 hi/lo [t][kp][b]
    {
        float (*tile)[I_ + 1] = (float (*)[I_ + 1])red;   // 64 x 129 in red
        for (int t = blockIdx.x; t < T_; t += GRID0) {
            __syncthreads();
            for (int idx = tid; idx < B_ * I_; idx += NT) {
                int b = idx >> 7, i = idx & 127;
                tile[b][i] = x[(b * T_ + t) * I_ + i];
            }
            __syncthreads();
            for (int idx = tid; idx < 64 * B_; idx += NT) {
                int kp = idx >> 6, b = idx & 63;
                float v0 = tile[b][2 * kp];
                float v1 = tile[b][2 * kp + 1];
                unsigned ph = bfpack(v0, v1);
                unsigned pl = bfpack(v0 - bflo(ph), v1 - bfhi(ph));
                g_xhb[t * 4096 + idx] = ph;
                g_xlb[t * 4096 + idx] = pl;
            }
        }
    }
    gridbar(sense);

    // ---- packed weight slices: Wt[kp][r] u32, r = gate*4 + c
    for (int idx = tid; idx < 320 * 16; idx += NT) {
        int kp = idx >> 4, r = idx & 15;
        int grow = (r >> 2) * H_ + hj0 + (r & 3);
        int k0 = 2 * kp, k1 = k0 + 1;
        float v0 = (k0 < I_) ? W_ih0[grow * I_ + k0] : W_hh0[grow * H_ + (k0 - I_)];
        float v1 = (k1 < I_) ? W_ih0[grow * I_ + k1] : W_hh0[grow * H_ + (k1 - I_)];
        unsigned ph = bfpack(v0, v1);
        WtH0[idx] = ph;
        WtL0[idx] = bfpack(v0 - bflo(ph), v1 - bfhi(ph));
    }
    for (int idx = tid; idx < 512 * 16; idx += NT) {
        int kp = idx >> 4, r = idx & 15;
        int grow = (r >> 2) * H_ + hj0 + (r & 3);
        int k0 = 2 * kp, k1 = k0 + 1;
        float v0 = (k0 < H_) ? W_ih1[grow * H_ + k0] : W_hh1[grow * H_ + (k0 - H_)];
        float v1 = (k1 < H_) ? W_ih1[grow * H_ + k1] : W_hh1[grow * H_ + (k1 - H_)];
        unsigned ph = bfpack(v0, v1);
        WtH1[idx] = ph;
        WtL1[idx] = bfpack(v0 - bflo(ph), v1 - bfhi(ph));
    }
    if (tid < 16) {
        int grow = (tid >> 2) * H_ + hj0 + (tid & 3);
        bias0[tid] = b_ih0[grow] + b_hh0[grow];
        bias1[tid] = b_ih1[grow] + b_hh1[grow];
    }
    __syncthreads();

    // ---- main loop: group0 layer0 at t=k, group1 layer1 at s=k-1 (concurrent)
    float2 cst = make_float2(0.f, 0.f);     // c-state for (row0, row1) of act unit
    ull* redG    = red + grp * 4096;
    float* gsG   = grp ? gs1 : gs0;
    float* biasG = grp ? bias1 : bias0;
    const int rp01_a = gtid >> 6;      // act unit (gtid<128): local row-pair 0..1
    const int b_a    = gtid & 63;      //                      batch 0..63

    for (int k = 0; k <= T_; ++k) {
        const bool active = grp ? (k >= 1) : (k < T_);
        if (active) {
            float c[4][2][4];
#pragma unroll
            for (int mt = 0; mt < 4; mt++)
#pragma unroll
                for (int nt = 0; nt < 2; nt++)
#pragma unroll
                    for (int i = 0; i < 4; i++) c[mt][nt][i] = 0.f;

            if (grp == 0) {
                // x segment: kp 0..63 of Wt0 (8 kp per warp, 1 step)
                gemmB(c, g_xhb + k * 4096, g_xlb + k * 4096,
                      WtH0, WtL0, wi * 8, 1, qd, tq);
                if (k > 0) {  // h0 segment: kp 64..319 (32 kp per warp, 4 steps)
                    int buf = ((k - 1) & 1) * 16384;
                    gemmB(c, g_h0hb + buf, g_h0lb + buf,
                          WtH0 + 64 * 16, WtL0 + 64 * 16, wi * 32, 4, qd, tq);
                }
            } else {
                // h0 segment: kp 0..255 of Wt1
                int buf = ((k - 1) & 1) * 16384;
                gemmB(c, g_h0hb + buf, g_h0lb + buf,
                      WtH1, WtL1, wi * 32, 4, qd, tq);
                if (k >= 2)  // h1 segment: kp 256..511
                    gemmB(c, g_h1hb + (k - 2) * 16384, g_h1lb + (k - 2) * 16384,
                          WtH1 + 256 * 16, WtL1 + 256 * 16, wi * 32, 4, qd, tq);
            }

            // dump C fragments: entry ull = rows (2rp, 2rp+1) @ batch b
            {
                ull* rw = redG + wi * 512;
#pragma unroll
                for (int mt = 0; mt < 4; mt++)
#pragma unroll
                    for (int nt = 0; nt < 2; nt++) {
                        int rp = nt * 4 + tq;
                        int b  = mt * 16 + qd;
                        rw[rp * 64 + b]     = pack_ab(c[mt][nt][0], c[mt][nt][1]);
                        rw[rp * 64 + b + 8] = pack_ab(c[mt][nt][2], c[mt][nt][3]);
                    }
            }
            if (grp == 0) GBAR1(); else GBAR2();

            // stage1: 256 threads, 2 units each (unit = row-pair x batch)
#pragma unroll
            for (int uu = 0; uu < 2; uu++) {
                int u = gtid + uu * 256;
                int rp = u >> 6, b = u & 63;
                const ull* rr = redG + rp * 64 + b;
                ull v = rr[0];
#pragma unroll
                for (int ww = 1; ww < 8; ww++) v = addx2(v, rr[ww * 512]);
                float2 bb = *(const float2*)(biasG + 2 * rp);
                v = addx2(v, pack_ab(bb.x, bb.y));
                gsG[(2 * rp) * 64 + b]     = lo2(v);
                gsG[(2 * rp + 1) * 64 + b] = hi2(v);
            }
            if (grp == 0) GBAR1(); else GBAR2();

            // activation: 128 threads; unit = (local row-pair rp01, batch b)
            if (gtid < 128) {
                const int r0 = 2 * rp01_a, r1 = r0 + 1;
                float xi0 = gsG[(0  + r0) * 64 + b_a], xi1 = gsG[(0  + r1) * 64 + b_a];
                float xf0 = gsG[(4  + r0) * 64 + b_a], xf1 = gsG[(4  + r1) * 64 + b_a];
                float xg0 = gsG[(8  + r0) * 64 + b_a], xg1 = gsG[(8  + r1) * 64 + b_a];
                float xo0 = gsG[(12 + r0) * 64 + b_a], xo1 = gsG[(12 + r1) * 64 + b_a];
                float i0 = sigm(xi0), i1 = sigm(xi1);
                float f0 = sigm(xf0), f1 = sigm(xf1);
                float g0 = tanh_(xg0), g1 = tanh_(xg1);
                float o0 = sigm(xo0), o1 = sigm(xo1);
                cst.x = f0 * cst.x + i0 * g0;
                cst.y = f1 * cst.y + i1 * g1;
                float h0v = o0 * tanh_(cst.x);
                float h1v = o1 * tanh_(cst.y);
                unsigned ph = bfpack(h0v, h1v);
                unsigned pl = bfpack(h0v - bflo(ph), h1v - bfhi(ph));
                int kp = (hj0 >> 1) + rp01_a;     // global k-pair index
                if (grp == 0) {
                    int buf = (k & 1) * 16384;
                    g_h0hb[buf + kp * B_ + b_a] = ph;
                    g_h0lb[buf + kp * B_ + b_a] = pl;
                } else {
                    int s = k - 1;
                    g_h1hb[s * 16384 + kp * B_ + b_a] = ph;
                    g_h1lb[s * 16384 + kp * B_ + b_a] = pl;
                    g_h1[s * H_ * B_ + (hj0 + r0) * B_ + b_a] = h0v;
                    g_h1[s * H_ * B_ + (hj0 + r1) * B_ + b_a] = h1v;
                }
            }
        }
        gridbar(sense);
    }

    // ---- FC phase: out[b][t][o] = sum_h h1[t][h][b] * Wfc[o][h] + bfc[o]
    {
        float* w_s = sm;                  // 128 x 65 = 8320
        float* h_s = sm + 8320;           // 64 x 64  = 4096
        float* o_s = sm + 12416;          // 64 x 128 = 8192
        const int ot = tid & 15;          // o = ot + j*16
        const int bt = (tid >> 4) & 15;   // batches bt*4..+3 (tid<256 only)

        for (int t = blockIdx.x; t < T_; t += GRID0) {
            ull acc[16];
#pragma unroll
            for (int i = 0; i < 16; i++) acc[i] = 0ull;

            for (int kb = 0; kb < H_; kb += 64) {
                __syncthreads();
                for (int idx = tid; idx < O_ * 64; idx += NT) {
                    int o = idx >> 6, kk = idx & 63;
                    w_s[o * 65 + kk] = Wfc[o * H_ + kb + kk];
                }
                for (int idx = tid; idx < 64 * B_; idx += NT) {
                    h_s[idx] = g_h1[(t * H_ + kb) * B_ + idx];
                }
                __syncthreads();
                if (tid < 256) {
#pragma unroll 4
                    for (int kk = 0; kk < 64; kk++) {
                        ulonglong2 A = *(const ulonglong2*)(h_s + kk * B_ + bt * 4);
#pragma unroll
                        for (int j = 0; j < 8; j++) {
                            ull ww = pack2(w_s[(ot + j * 16) * 65 + kk]);
                            ffma2(acc[j * 2 + 0], A.x, ww);
                            ffma2(acc[j * 2 + 1], A.y, ww);
                        }
                    }
                }
            }
            __syncthreads();
            if (tid < 256) {
#pragma unroll
                for (int j = 0; j < 8; j++) {
                    int o = ot + j * 16;
                    o_s[(bt * 4 + 0) * O_ + o] = lo2(acc[j * 2 + 0]);
                    o_s[(bt * 4 + 1) * O_ + o] = hi2(acc[j * 2 + 0]);
                    o_s[(bt * 4 + 2) * O_ + o] = lo2(acc[j * 2 + 1]);
                    o_s[(bt * 4 + 3) * O_ + o] = hi2(acc[j * 2 + 1]);
                }
            }
            __syncthreads();
            for (int idx = tid; idx < B_ * O_; idx += NT) {
                int b = idx >> 7, o = idx & 127;
                out[(b * T_ + t) * O_ + o] = o_s[idx] + __ldg(&bfc[o]);
            }
        }
    }
}

// ---------------------------------------------------------------------------
extern "C" void kernel_launch(void* const* d_in, const int* in_sizes, int n_in,
                              void* d_out, int out_size) {
    const float* x     = (const float*)d_in[0];
    const float* W_ih0 = (const float*)d_in[1];
    const float* W_hh0 = (const float*)d_in[2];
    const float* b_ih0 = (const float*)d_in[3];
    const float* b_hh0 = (const float*)d_in[4];
    const float* W_ih1 = (const float*)d_in[5];
    const float* W_hh1 = (const float*)d_in[6];
    const float* b_ih1 = (const float*)d_in[7];
    const float* b_hh1 = (const float*)d_in[8];
    const float* W_fc  = (const float*)d_in[9];
    const float* b_fc  = (const float*)d_in[10];
    float* out = (float*)d_out;

    size_t smem = (size_t)(28704 * 4 + 65536);   // 180352 B
    cudaFuncSetAttribute(mega_kernel, cudaFuncAttributeMaxDynamicSharedMemorySize, (int)smem);

    mega_kernel<<<GRID0, NT, smem>>>(x, W_ih0, W_hh0, b_ih0, b_hh0,
                                     W_ih1, W_hh1, b_ih1, b_hh1,
                                     W_fc, b_fc, out);
}

// round 17
// speedup vs baseline: 1.3900x; 1.1253x over previous
#include <cuda_runtime.h>
#include <math.h>

#define B_ 64
#define T_ 1024
#define I_ 128
#define H_ 512
#define O_ 128
#define GRID0 128
#define NT 512

typedef unsigned long long ull;

// ---- scratch (device globals: allocation-free) ----
// interleaved bf16 split buffers: .x = hi pack, .y = lo pack, layout [t][kp][b]
__device__ uint2 g_xI[T_ * 64 * B_];
__device__ uint2 g_h0I[2 * 256 * B_];
__device__ uint2 g_h1I[T_ * 256 * B_];
__device__ float g_h1[T_ * H_ * B_];     // layer1 h fp32 (FC input)
__device__ unsigned g_bar_count;
__device__ unsigned g_bar_sense;

// ---- packed f32x2 helpers (FC phase + reduction) ----
__device__ __forceinline__ ull pack2(float x) {
    ull r; unsigned u = __float_as_uint(x);
    asm("mov.b64 %0, {%1, %1};" : "=l"(r) : "r"(u));
    return r;
}
__device__ __forceinline__ ull pack_ab(float a, float b) {
    ull r;
    asm("mov.b64 %0, {%1, %2};" : "=l"(r)
        : "r"(__float_as_uint(a)), "r"(__float_as_uint(b)));
    return r;
}
__device__ __forceinline__ void ffma2(ull &acc, ull a, ull w) {
    asm("fma.rn.f32x2 %0, %1, %2, %0;" : "+l"(acc) : "l"(a), "l"(w));
}
__device__ __forceinline__ ull addx2(ull a, ull b) {
    ull r;
    asm("add.rn.f32x2 %0, %1, %2;" : "=l"(r) : "l"(a), "l"(b));
    return r;
}
__device__ __forceinline__ float lo2(ull v) { return __uint_as_float((unsigned)v); }
__device__ __forceinline__ float hi2(ull v) { return __uint_as_float((unsigned)(v >> 32)); }

// ---- bf16 pack helpers: u32 = {hi16 = bf16(vhi), lo16 = bf16(vlo)} ----
__device__ __forceinline__ unsigned bfpack(float vlo, float vhi) {
    unsigned r;
    asm("cvt.rn.bf16x2.f32 %0, %1, %2;" : "=r"(r) : "f"(vhi), "f"(vlo));
    return r;
}
__device__ __forceinline__ float bflo(unsigned p) { return __uint_as_float(p << 16); }
__device__ __forceinline__ float bfhi(unsigned p) { return __uint_as_float(p & 0xffff0000u); }

__device__ __forceinline__ float sigm(float x) {
    return __fdividef(1.f, 1.f + __expf(-x));
}
__device__ __forceinline__ float tanh_(float x) {
    return __fdividef(2.f, 1.f + __expf(-2.f * x)) - 1.f;
}

#define GBAR1() asm volatile("bar.sync 1, 256;" ::: "memory")
#define GBAR2() asm volatile("bar.sync 2, 256;" ::: "memory")

// ---- full grid barrier (identical to R12/R14/R16 passing kernels) ----
__device__ __forceinline__ void gridbar(unsigned &sense) {
    __syncthreads();
    if (threadIdx.x == 0) {
        unsigned s = sense ^ 1u;
        sense = s;
        unsigned old;
        asm volatile("atom.release.gpu.global.add.u32 %0, [%1], %2;"
                     : "=r"(old) : "l"(&g_bar_count), "r"(1u));
        if (old == GRID0 - 1u) {
            g_bar_count = 0u;
            asm volatile("st.release.gpu.global.u32 [%0], %1;"
                         :: "l"(&g_bar_sense), "r"(s));
        } else {
            unsigned v;
            do {
                asm volatile("ld.acquire.gpu.global.u32 %0, [%1];"
                             : "=r"(v) : "l"(&g_bar_sense));
            } while (v != s);
        }
    }
    __syncthreads();
}

// ---- bf16 m16n8k16 MMA ----
__device__ __forceinline__ void mma16(float* c,
    unsigned a0, unsigned a1, unsigned a2, unsigned a3,
    unsigned b0, unsigned b1)
{
    asm volatile(
        "mma.sync.aligned.m16n8k16.row.col.f32.bf16.bf16.f32 "
        "{%0,%1,%2,%3}, {%4,%5,%6,%7}, {%8,%9}, {%0,%1,%2,%3};"
        : "+f"(c[0]), "+f"(c[1]), "+f"(c[2]), "+f"(c[3])
        : "r"(a0), "r"(a1), "r"(a2), "r"(a3), "r"(b0), "r"(b1));
}

// ---- A fragment: 4 interleaved hi/lo k-pair packs ----
struct AF { uint2 q0, q1, q2, q3; };
__device__ __forceinline__ AF ldA(const uint2* base) {
    AF f;
    f.q0 = __ldcg(base);
    f.q1 = __ldcg(base + 8);
    f.q2 = __ldcg(base + 4 * B_);
    f.q3 = __ldcg(base + 4 * B_ + 8);
    return f;
}

// ---- split-bf16 gate GEMM, register-pipelined (1-step prefetch distance) ----
// A[m=batch][k]: srcI[kp][b] uint2 (.x hi pack, .y lo pack), global .cg.
// B[k][n=gaterow]: WH/WL[kp][16] u32 (smem).
// Warp covers kp in [kp0, kp0 + nsteps*8). Lane: qd = lane>>2, tq = lane&3.
// c[mt][nt][4]: batches 16mt+{qd,qd+8}, gate rows 8nt+{2tq,2tq+1}.
__device__ __forceinline__ void gemmP(
    float c[4][2][4], const uint2* __restrict__ srcI,
    const unsigned* __restrict__ WH, const unsigned* __restrict__ WL,
    int kp0, int nsteps, int qd, int tq)
{
    const uint2* ab = srcI + (kp0 + tq) * B_ + qd;
    AF f[4];
#pragma unroll
    for (int mt = 0; mt < 4; mt++)
        f[mt] = ldA(ab + mt * 16);

    for (int s = 0; s < nsteps; s++) {
        const unsigned* wh = WH + (kp0 + s * 8 + tq) * 16;
        const unsigned* wl = WL + (kp0 + s * 8 + tq) * 16;
        unsigned bh0[2], bh1[2], bl0[2], bl1[2];
#pragma unroll
        for (int nt = 0; nt < 2; nt++) {
            int n = nt * 8 + qd;
            bh0[nt] = wh[n]; bh1[nt] = wh[64 + n];
            bl0[nt] = wl[n]; bl1[nt] = wl[64 + n];
        }
        const bool more = (s + 1 < nsteps);
        const uint2* nb = ab + (s + 1) * (8 * B_);
#pragma unroll
        for (int mt = 0; mt < 4; mt++) {
            AF cur = f[mt];
            if (more) f[mt] = ldA(nb + mt * 16);   // prefetch step s+1
#pragma unroll
            for (int nt = 0; nt < 2; nt++) {
                mma16(c[mt][nt], cur.q0.x, cur.q1.x, cur.q2.x, cur.q3.x,
                      bh0[nt], bh1[nt]);
                mma16(c[mt][nt], cur.q0.y, cur.q1.y, cur.q2.y, cur.q3.y,
                      bh0[nt], bh1[nt]);
                mma16(c[mt][nt], cur.q0.x, cur.q1.x, cur.q2.x, cur.q3.x,
                      bl0[nt], bl1[nt]);
            }
        }
    }
}

// ---------------------------------------------------------------------------
// Mega kernel: transpose + both LSTM layers (warp-specialized, bf16 MMA) + FC.
__global__ void __launch_bounds__(NT, 1) mega_kernel(
    const float* __restrict__ x,
    const float* __restrict__ W_ih0, const float* __restrict__ W_hh0,
    const float* __restrict__ b_ih0, const float* __restrict__ b_hh0,
    const float* __restrict__ W_ih1, const float* __restrict__ W_hh1,
    const float* __restrict__ b_ih1, const float* __restrict__ b_hh1,
    const float* __restrict__ Wfc,  const float* __restrict__ bfc,
    float* __restrict__ out)
{
    extern __shared__ float sm[];
    unsigned* WtH0 = (unsigned*)sm;            // [320][16] = 5120 u32
    unsigned* WtL0 = (unsigned*)sm + 5120;     // 5120
    unsigned* WtH1 = (unsigned*)sm + 10240;    // [512][16] = 8192
    unsigned* WtL1 = (unsigned*)sm + 18432;    // 8192  -> ends at 26624
    float* bias0 = sm + 26624;                 // 16
    float* bias1 = sm + 26640;                 // 16
    float* gs0   = sm + 26656;                 // 16 x 64 = 1024
    float* gs1   = sm + 27680;                 // 16 x 64 = 1024
    ull*   red   = (ull*)(sm + 28704);         // 2 * 8 * 512 ull = 65536 B

    const int tid  = threadIdx.x;
    const int hj0  = blockIdx.x * 4;
    const int grp  = tid >> 8;         // 0: layer0, 1: layer1
    const int gtid = tid & 255;
    const int wi   = gtid >> 5;        // group-warp 0..7
    const int lane = gtid & 31;
    const int qd   = lane >> 2;        // mma quad 0..7
    const int tq   = lane & 3;         // thread-in-quad 0..3

    unsigned sense = 0;
    if (tid == 0) sense = *(volatile unsigned*)&g_bar_sense;

    // ---- transpose phase: x[b][t][i] -> packed interleaved bf16 [t][kp][b]
    {
        float (*tile)[I_ + 1] = (float (*)[I_ + 1])red;   // 64 x 129 in red
        for (int t = blockIdx.x; t < T_; t += GRID0) {
            __syncthreads();
            for (int idx = tid; idx < B_ * I_; idx += NT) {
                int b = idx >> 7, i = idx & 127;
                tile[b][i] = x[(b * T_ + t) * I_ + i];
            }
            __syncthreads();
            for (int idx = tid; idx < 64 * B_; idx += NT) {
                int kp = idx >> 6, b = idx & 63;
                float v0 = tile[b][2 * kp];
                float v1 = tile[b][2 * kp + 1];
                unsigned ph = bfpack(v0, v1);
                unsigned pl = bfpack(v0 - bflo(ph), v1 - bfhi(ph));
                g_xI[t * 4096 + idx] = make_uint2(ph, pl);
            }
        }
    }
    gridbar(sense);

    // ---- packed weight slices: Wt[kp][r] u32, r = gate*4 + c
    for (int idx = tid; idx < 320 * 16; idx += NT) {
        int kp = idx >> 4, r = idx & 15;
        int grow = (r >> 2) * H_ + hj0 + (r & 3);
        int k0 = 2 * kp, k1 = k0 + 1;
        float v0 = (k0 < I_) ? W_ih0[grow * I_ + k0] : W_hh0[grow * H_ + (k0 - I_)];
        float v1 = (k1 < I_) ? W_ih0[grow * I_ + k1] : W_hh0[grow * H_ + (k1 - I_)];
        unsigned ph = bfpack(v0, v1);
        WtH0[idx] = ph;
        WtL0[idx] = bfpack(v0 - bflo(ph), v1 - bfhi(ph));
    }
    for (int idx = tid; idx < 512 * 16; idx += NT) {
        int kp = idx >> 4, r = idx & 15;
        int grow = (r >> 2) * H_ + hj0 + (r & 3);
        int k0 = 2 * kp, k1 = k0 + 1;
        float v0 = (k0 < H_) ? W_ih1[grow * H_ + k0] : W_hh1[grow * H_ + (k0 - H_)];
        float v1 = (k1 < H_) ? W_ih1[grow * H_ + k1] : W_hh1[grow * H_ + (k1 - H_)];
        unsigned ph = bfpack(v0, v1);
        WtH1[idx] = ph;
        WtL1[idx] = bfpack(v0 - bflo(ph), v1 - bfhi(ph));
    }
    if (tid < 16) {
        int grow = (tid >> 2) * H_ + hj0 + (tid & 3);
        bias0[tid] = b_ih0[grow] + b_hh0[grow];
        bias1[tid] = b_ih1[grow] + b_hh1[grow];
    }
    __syncthreads();

    // ---- main loop: group0 layer0 at t=k, group1 layer1 at s=k-1 (concurrent)
    float2 cst = make_float2(0.f, 0.f);
    ull* redG    = red + grp * 4096;
    float* gsG   = grp ? gs1 : gs0;
    float* biasG = grp ? bias1 : bias0;
    const int rp01_a = gtid >> 6;      // act unit (gtid<128): local row-pair 0..1
    const int b_a    = gtid & 63;      //                      batch 0..63

    for (int k = 0; k <= T_; ++k) {
        const bool active = grp ? (k >= 1) : (k < T_);
        if (active) {
            float c[4][2][4];
#pragma unroll
            for (int mt = 0; mt < 4; mt++)
#pragma unroll
                for (int nt = 0; nt < 2; nt++)
#pragma unroll
                    for (int i = 0; i < 4; i++) c[mt][nt][i] = 0.f;

            if (grp == 0) {
                // x segment: kp 0..63 of Wt0 (8 kp per warp, 1 step)
                gemmP(c, g_xI + k * 4096, WtH0, WtL0, wi * 8, 1, qd, tq);
                if (k > 0) {  // h0 segment: kp 64..319 (32 kp per warp, 4 steps)
                    int buf = ((k - 1) & 1) * 16384;
                    gemmP(c, g_h0I + buf,
                          WtH0 + 64 * 16, WtL0 + 64 * 16, wi * 32, 4, qd, tq);
                }
            } else {
                // h0 segment: kp 0..255 of Wt1
                int buf = ((k - 1) & 1) * 16384;
                gemmP(c, g_h0I + buf, WtH1, WtL1, wi * 32, 4, qd, tq);
                if (k >= 2)  // h1 segment: kp 256..511
                    gemmP(c, g_h1I + (k - 2) * 16384,
                          WtH1 + 256 * 16, WtL1 + 256 * 16, wi * 32, 4, qd, tq);
            }

            // dump C fragments: entry ull = rows (2rp, 2rp+1) @ batch b
            {
                ull* rw = redG + wi * 512;
#pragma unroll
                for (int mt = 0; mt < 4; mt++)
#pragma unroll
                    for (int nt = 0; nt < 2; nt++) {
                        int rp = nt * 4 + tq;
                        int b  = mt * 16 + qd;
                        rw[rp * 64 + b]     = pack_ab(c[mt][nt][0], c[mt][nt][1]);
                        rw[rp * 64 + b + 8] = pack_ab(c[mt][nt][2], c[mt][nt][3]);
                    }
            }
            if (grp == 0) GBAR1(); else GBAR2();

            // stage1: 256 threads, 2 units each (unit = row-pair x batch)
#pragma unroll
            for (int uu = 0; uu < 2; uu++) {
                int u = gtid + uu * 256;
                int rp = u >> 6, b = u & 63;
                const ull* rr = redG + rp * 64 + b;
                ull v = rr[0];
#pragma unroll
                for (int ww = 1; ww < 8; ww++) v = addx2(v, rr[ww * 512]);
                float2 bb = *(const float2*)(biasG + 2 * rp);
                v = addx2(v, pack_ab(bb.x, bb.y));
                gsG[(2 * rp) * 64 + b]     = lo2(v);
                gsG[(2 * rp + 1) * 64 + b] = hi2(v);
            }
            if (grp == 0) GBAR1(); else GBAR2();

            // activation: 128 threads; unit = (local row-pair rp01, batch b)
            if (gtid < 128) {
                const int r0 = 2 * rp01_a, r1 = r0 + 1;
                float xi0 = gsG[(0  + r0) * 64 + b_a], xi1 = gsG[(0  + r1) * 64 + b_a];
                float xf0 = gsG[(4  + r0) * 64 + b_a], xf1 = gsG[(4  + r1) * 64 + b_a];
                float xg0 = gsG[(8  + r0) * 64 + b_a], xg1 = gsG[(8  + r1) * 64 + b_a];
                float xo0 = gsG[(12 + r0) * 64 + b_a], xo1 = gsG[(12 + r1) * 64 + b_a];
                float i0 = sigm(xi0), i1 = sigm(xi1);
                float f0 = sigm(xf0), f1 = sigm(xf1);
                float g0 = tanh_(xg0), g1 = tanh_(xg1);
                float o0 = sigm(xo0), o1 = sigm(xo1);
                cst.x = f0 * cst.x + i0 * g0;
                cst.y = f1 * cst.y + i1 * g1;
                float h0v = o0 * tanh_(cst.x);
                float h1v = o1 * tanh_(cst.y);
                unsigned ph = bfpack(h0v, h1v);
                unsigned pl = bfpack(h0v - bflo(ph), h1v - bfhi(ph));
                int kp = (hj0 >> 1) + rp01_a;     // global k-pair index
                if (grp == 0) {
                    int buf = (k & 1) * 16384;
                    g_h0I[buf + kp * B_ + b_a] = make_uint2(ph, pl);
                } else {
                    int s = k - 1;
                    g_h1I[s * 16384 + kp * B_ + b_a] = make_uint2(ph, pl);
                    g_h1[s * H_ * B_ + (hj0 + r0) * B_ + b_a] = h0v;
                    g_h1[s * H_ * B_ + (hj0 + r1) * B_ + b_a] = h1v;
                }
            }
        }
        gridbar(sense);
    }

    // ---- FC phase: out[b][t][o] = sum_h h1[t][h][b] * Wfc[o][h] + bfc[o]
    {
        float* w_s = sm;                  // 128 x 65 = 8320
        float* h_s = sm + 8320;           // 64 x 64  = 4096
        float* o_s = sm + 12416;          // 64 x 128 = 8192
        const int ot = tid & 15;          // o = ot + j*16
        const int bt = (tid >> 4) & 15;   // batches bt*4..+3 (tid<256 only)

        for (int t = blockIdx.x; t < T_; t += GRID0) {
            ull acc[16];
#pragma unroll
            for (int i = 0; i < 16; i++) acc[i] = 0ull;

            for (int kb = 0; kb < H_; kb += 64) {
                __syncthreads();
                for (int idx = tid; idx < O_ * 64; idx += NT) {
                    int o = idx >> 6, kk = idx & 63;
                    w_s[o * 65 + kk] = Wfc[o * H_ + kb + kk];
                }
                for (int idx = tid; idx < 64 * B_; idx += NT) {
                    h_s[idx] = g_h1[(t * H_ + kb) * B_ + idx];
                }
                __syncthreads();
                if (tid < 256) {
#pragma unroll 4
                    for (int kk = 0; kk < 64; kk++) {
                        ulonglong2 A = *(const ulonglong2*)(h_s + kk * B_ + bt * 4);
#pragma unroll
                        for (int j = 0; j < 8; j++) {
                            ull ww = pack2(w_s[(ot + j * 16) * 65 + kk]);
                            ffma2(acc[j * 2 + 0], A.x, ww);
                            ffma2(acc[j * 2 + 1], A.y, ww);
                        }
                    }
                }
            }
            __syncthreads();
            if (tid < 256) {
#pragma unroll
                for (int j = 0; j < 8; j++) {
                    int o = ot + j * 16;
                    o_s[(bt * 4 + 0) * O_ + o] = lo2(acc[j * 2 + 0]);
                    o_s[(bt * 4 + 1) * O_ + o] = hi2(acc[j * 2 + 0]);
                    o_s[(bt * 4 + 2) * O_ + o] = lo2(acc[j * 2 + 1]);
                    o_s[(bt * 4 + 3) * O_ + o] = hi2(acc[j * 2 + 1]);
                }
            }
            __syncthreads();
            for (int idx = tid; idx < B_ * O_; idx += NT) {
                int b = idx >> 7, o = idx & 127;
                out[(b * T_ + t) * O_ + o] = o_s[idx] + __ldg(&bfc[o]);
            }
        }
    }
}

// ---------------------------------------------------------------------------
extern "C" void kernel_launch(void* const* d_in, const int* in_sizes, int n_in,
                              void* d_out, int out_size) {
    const float* x     = (const float*)d_in[0];
    const float* W_ih0 = (const float*)d_in[1];
    const float* W_hh0 = (const float*)d_in[2];
    const float* b_ih0 = (const float*)d_in[3];
    const float* b_hh0 = (const float*)d_in[4];
    const float* W_ih1 = (const float*)d_in[5];
    const float* W_hh1 = (const float*)d_in[6];
    const float* b_ih1 = (const float*)d_in[7];
    const float* b_hh1 = (const float*)d_in[8];
    const float* W_fc  = (const float*)d_in[9];
    const float* b_fc  = (const float*)d_in[10];
    float* out = (float*)d_out;

    size_t smem = (size_t)(28704 * 4 + 65536);   // 180352 B
    cudaFuncSetAttribute(mega_kernel, cudaFuncAttributeMaxDynamicSharedMemorySize, (int)smem);

    mega_kernel<<<GRID0, NT, smem>>>(x, W_ih0, W_hh0, b_ih0, b_hh0,
                                     W_ih1, W_hh1, b_ih1, b_hh1,
                                     W_fc, b_fc, out);
}